// round 4
// baseline (speedup 1.0000x reference)
#include <cuda_runtime.h>
#include <cuda_bf16.h>
#include <cstdint>

// Statically zero-initialized accumulators; the last finishing block resets
// them to zero after producing the output, so every graph replay starts from
// the same state (determinism requirement).
__device__ double             g_total = 0.0;
__device__ unsigned long long g_count = 0ull;
__device__ unsigned int       g_done  = 0u;

// One warp per row. Lanes stride float4 across the 512-wide row (4 iters).
// Rows whose label >= num_old are skipped entirely (their embedding row is
// never read), halving HBM traffic for uniform labels. Single fused kernel:
// block-level reduce -> global double atomic -> last-block finalize + reset.
__global__ __launch_bounds__(256)
void fused_mse_kernel(const float* __restrict__ emb,
                      const float* __restrict__ cen,
                      const int*   __restrict__ labels,
                      const int*   __restrict__ num_old_p,
                      int batch,
                      float* __restrict__ out)
{
    const int num_old = *num_old_p;

    const int warp_global = (blockIdx.x * blockDim.x + threadIdx.x) >> 5;
    const int lane        = threadIdx.x & 31;

    __shared__ double       s_total;
    __shared__ unsigned int s_count;
    if (threadIdx.x == 0) { s_total = 0.0; s_count = 0u; }
    __syncthreads();

    if (warp_global < batch) {
        const int row   = warp_global;
        const int label = labels[row];
        if (label < num_old) {
            const float4* e = reinterpret_cast<const float4*>(emb) + (size_t)row   * 128;
            const float4* c = reinterpret_cast<const float4*>(cen) + (size_t)label * 128;
            float acc = 0.0f;
            #pragma unroll
            for (int i = 0; i < 4; i++) {
                float4 ev = e[lane + 32 * i];
                float4 cv = c[lane + 32 * i];
                float dx = ev.x - cv.x;
                float dy = ev.y - cv.y;
                float dz = ev.z - cv.z;
                float dw = ev.w - cv.w;
                acc = fmaf(dx, dx, acc);
                acc = fmaf(dy, dy, acc);
                acc = fmaf(dz, dz, acc);
                acc = fmaf(dw, dw, acc);
            }
            // Warp reduce.
            #pragma unroll
            for (int off = 16; off > 0; off >>= 1)
                acc += __shfl_xor_sync(0xFFFFFFFFu, acc, off);

            if (lane == 0) {
                atomicAdd(&s_total, (double)acc * (1.0 / 512.0));
                atomicAdd(&s_count, 1u);
            }
        }
    }
    __syncthreads();

    if (threadIdx.x == 0) {
        if (s_count > 0u) {
            atomicAdd(&g_total, s_total);
            atomicAdd(&g_count, (unsigned long long)s_count);
        }
        // Make this block's contributions visible before taking a ticket.
        __threadfence();
        unsigned int ticket = atomicAdd(&g_done, 1u);
        if (ticket == gridDim.x - 1u) {
            // Last block: all other blocks' atomics are visible (each fenced
            // before its ticket increment).
            const double             t = g_total;
            const unsigned long long c = g_count;
            out[0] = (c == 0ull) ? (float)t : (float)(t / (double)c);
            // Reset for the next graph replay.
            g_total = 0.0;
            g_count = 0ull;
            g_done  = 0u;
        }
    }
}

extern "C" void kernel_launch(void* const* d_in, const int* in_sizes, int n_in,
                              void* d_out, int out_size)
{
    const float* emb       = (const float*)d_in[0];
    const float* cen       = (const float*)d_in[1];
    const int*   labels    = (const int*)d_in[2];
    const int*   num_old_p = (const int*)d_in[3];
    float*       out       = (float*)d_out;

    const int dim   = 512;
    const int batch = in_sizes[0] / dim;   // 65536

    const int warps_per_block = 256 / 32;                              // 8 rows/block
    const int grid = (batch + warps_per_block - 1) / warps_per_block;  // 8192
    fused_mse_kernel<<<grid, 256>>>(emb, cen, labels, num_old_p, batch, out);
}

// round 5
// speedup vs baseline: 1.3088x; 1.3088x over previous
#include <cuda_runtime.h>
#include <cuda_bf16.h>
#include <cstdint>

// Statically zero-initialized accumulators; last block resets them after
// writing the output so graph replays are deterministic.
__device__ double             g_total = 0.0;
__device__ unsigned long long g_count = 0ull;
__device__ unsigned int       g_done  = 0u;

#define ROWS_PER_WARP 16

__global__ __launch_bounds__(256)
void fused_mse_kernel(const float* __restrict__ emb,
                      const float* __restrict__ cen,
                      const int*   __restrict__ labels,
                      const int*   __restrict__ num_old_p,
                      int batch,
                      float* __restrict__ out)
{
    const int num_old = *num_old_p;
    const int warp_id = (blockIdx.x * blockDim.x + threadIdx.x) >> 5;
    const int lane    = threadIdx.x & 31;
    const int base    = warp_id * ROWS_PER_WARP;

    __shared__ double       s_total;
    __shared__ unsigned int s_count;
    if (threadIdx.x == 0) { s_total = 0.0; s_count = 0u; }
    __syncthreads();

    float acc0 = 0.0f, acc1 = 0.0f;
    int   cnt  = 0;

    if (base < batch) {
        // One coalesced label fetch for the warp's 16 rows.
        int my_label = 0x7FFFFFFF;
        if (lane < ROWS_PER_WARP && base + lane < batch)
            my_label = labels[base + lane];

        #pragma unroll
        for (int i = 0; i < ROWS_PER_WARP; i += 2) {
            const int  l0 = __shfl_sync(0xFFFFFFFFu, my_label, i);
            const int  l1 = __shfl_sync(0xFFFFFFFFu, my_label, i + 1);
            const bool a0 = (l0 < num_old);
            const bool a1 = (l1 < num_old);

            float4 e00, e01, e02, e03, c00, c01, c02, c03;
            float4 e10, e11, e12, e13, c10, c11, c12, c13;

            // Batch all loads for both rows before any compute -> deep MLP.
            if (a0) {
                const float4* e = reinterpret_cast<const float4*>(emb) + (size_t)(base + i) * 128;
                const float4* c = reinterpret_cast<const float4*>(cen) + (size_t)l0 * 128;
                e00 = __ldcs(e + lane);      e01 = __ldcs(e + lane + 32);
                e02 = __ldcs(e + lane + 64); e03 = __ldcs(e + lane + 96);
                c00 = c[lane];      c01 = c[lane + 32];
                c02 = c[lane + 64]; c03 = c[lane + 96];
            }
            if (a1) {
                const float4* e = reinterpret_cast<const float4*>(emb) + (size_t)(base + i + 1) * 128;
                const float4* c = reinterpret_cast<const float4*>(cen) + (size_t)l1 * 128;
                e10 = __ldcs(e + lane);      e11 = __ldcs(e + lane + 32);
                e12 = __ldcs(e + lane + 64); e13 = __ldcs(e + lane + 96);
                c10 = c[lane];      c11 = c[lane + 32];
                c12 = c[lane + 64]; c13 = c[lane + 96];
            }
            if (a0) {
                float d;
                d = e00.x - c00.x; acc0 = fmaf(d, d, acc0);
                d = e00.y - c00.y; acc0 = fmaf(d, d, acc0);
                d = e00.z - c00.z; acc0 = fmaf(d, d, acc0);
                d = e00.w - c00.w; acc0 = fmaf(d, d, acc0);
                d = e01.x - c01.x; acc0 = fmaf(d, d, acc0);
                d = e01.y - c01.y; acc0 = fmaf(d, d, acc0);
                d = e01.z - c01.z; acc0 = fmaf(d, d, acc0);
                d = e01.w - c01.w; acc0 = fmaf(d, d, acc0);
                d = e02.x - c02.x; acc0 = fmaf(d, d, acc0);
                d = e02.y - c02.y; acc0 = fmaf(d, d, acc0);
                d = e02.z - c02.z; acc0 = fmaf(d, d, acc0);
                d = e02.w - c02.w; acc0 = fmaf(d, d, acc0);
                d = e03.x - c03.x; acc0 = fmaf(d, d, acc0);
                d = e03.y - c03.y; acc0 = fmaf(d, d, acc0);
                d = e03.z - c03.z; acc0 = fmaf(d, d, acc0);
                d = e03.w - c03.w; acc0 = fmaf(d, d, acc0);
                cnt++;
            }
            if (a1) {
                float d;
                d = e10.x - c10.x; acc1 = fmaf(d, d, acc1);
                d = e10.y - c10.y; acc1 = fmaf(d, d, acc1);
                d = e10.z - c10.z; acc1 = fmaf(d, d, acc1);
                d = e10.w - c10.w; acc1 = fmaf(d, d, acc1);
                d = e11.x - c11.x; acc1 = fmaf(d, d, acc1);
                d = e11.y - c11.y; acc1 = fmaf(d, d, acc1);
                d = e11.z - c11.z; acc1 = fmaf(d, d, acc1);
                d = e11.w - c11.w; acc1 = fmaf(d, d, acc1);
                d = e12.x - c12.x; acc1 = fmaf(d, d, acc1);
                d = e12.y - c12.y; acc1 = fmaf(d, d, acc1);
                d = e12.z - c12.z; acc1 = fmaf(d, d, acc1);
                d = e12.w - c12.w; acc1 = fmaf(d, d, acc1);
                d = e13.x - c13.x; acc1 = fmaf(d, d, acc1);
                d = e13.y - c13.y; acc1 = fmaf(d, d, acc1);
                d = e13.z - c13.z; acc1 = fmaf(d, d, acc1);
                d = e13.w - c13.w; acc1 = fmaf(d, d, acc1);
                cnt++;
            }
        }
    }

    // Single warp reduction for the whole warp's 16 rows.
    float acc = acc0 + acc1;
    #pragma unroll
    for (int off = 16; off > 0; off >>= 1)
        acc += __shfl_xor_sync(0xFFFFFFFFu, acc, off);

    if (lane == 0 && cnt > 0) {
        atomicAdd(&s_total, (double)acc * (1.0 / 512.0));
        atomicAdd(&s_count, (unsigned int)cnt);
    }
    __syncthreads();

    if (threadIdx.x == 0) {
        if (s_count > 0u) {
            atomicAdd(&g_total, s_total);
            atomicAdd(&g_count, (unsigned long long)s_count);
        }
        __threadfence();
        unsigned int ticket = atomicAdd(&g_done, 1u);
        if (ticket == gridDim.x - 1u) {
            const double             t = g_total;
            const unsigned long long c = g_count;
            out[0] = (c == 0ull) ? (float)t : (float)(t / (double)c);
            g_total = 0.0;
            g_count = 0ull;
            g_done  = 0u;
        }
    }
}

extern "C" void kernel_launch(void* const* d_in, const int* in_sizes, int n_in,
                              void* d_out, int out_size)
{
    const float* emb       = (const float*)d_in[0];
    const float* cen       = (const float*)d_in[1];
    const int*   labels    = (const int*)d_in[2];
    const int*   num_old_p = (const int*)d_in[3];
    float*       out       = (float*)d_out;

    const int dim   = 512;
    const int batch = in_sizes[0] / dim;   // 65536

    const int rows_per_block = (256 / 32) * ROWS_PER_WARP;                 // 128
    const int grid = (batch + rows_per_block - 1) / rows_per_block;        // 512
    fused_mse_kernel<<<grid, 256>>>(emb, cen, labels, num_old_p, batch, out);
}